// round 15
// baseline (speedup 1.0000x reference)
#include <cuda_runtime.h>
#include <cuda_bf16.h>
#include <cstdint>

typedef unsigned long long u64;

#define B_      32
#define QL      4
#define DIM     2048
#define HEADS   16
#define HD      128
#define KVL     8192
#define M_      (B_*QL)
#define NQKV    2304
#define ASPL9   9                /* attention KV splits (288 CTAs ~ 2/SM)  */
#define SCALE   0.08838834764831845f
#define SMAX    16.0f

/* ------------------------------------------------------------------ */
__device__ float g_qkv[M_ * NQKV];                      /* q | k_new | v_new */
__device__ float g_po [(size_t)B_ * 64 * ASPL9 * HD];
__device__ float g_pml[B_ * 64 * ASPL9];
__device__ float g_o  [M_ * DIM];

/* ---------------- mma.sync helpers -------------------------------- */
__device__ __forceinline__ void ldsm_x4(uint32_t* a, uint32_t addr) {
    asm volatile("ldmatrix.sync.aligned.m8n8.x4.shared.b16 {%0,%1,%2,%3}, [%4];"
        : "=r"(a[0]), "=r"(a[1]), "=r"(a[2]), "=r"(a[3]) : "r"(addr));
}
__device__ __forceinline__ void ldsm_x4t(uint32_t* a, uint32_t addr) {
    asm volatile("ldmatrix.sync.aligned.m8n8.x4.trans.shared.b16 {%0,%1,%2,%3}, [%4];"
        : "=r"(a[0]), "=r"(a[1]), "=r"(a[2]), "=r"(a[3]) : "r"(addr));
}
__device__ __forceinline__ void mma_bf16(float* c, const uint32_t* a,
                                         uint32_t b0, uint32_t b1) {
    asm volatile("mma.sync.aligned.m16n8k16.row.col.f32.bf16.bf16.f32 "
        "{%0,%1,%2,%3}, {%4,%5,%6,%7}, {%8,%9}, {%0,%1,%2,%3};"
        : "+f"(c[0]), "+f"(c[1]), "+f"(c[2]), "+f"(c[3])
        : "r"(a[0]), "r"(a[1]), "r"(a[2]), "r"(a[3]), "r"(b0), "r"(b1));
}

__device__ __forceinline__ uint32_t bfpair(float a, float b) {
    __nv_bfloat162 t = __floats2bfloat162_rn(a, b);
    return *(uint32_t*)&t;
}
__device__ __forceinline__ uint32_t hipair(float a, float b, uint32_t& lo) {
    __nv_bfloat16 ha = __float2bfloat16(a), hb = __float2bfloat16(b);
    lo = bfpair(a - __bfloat162float(ha), b - __bfloat162float(hb));
    __nv_bfloat162 h; h.x = ha; h.y = hb;
    return *(uint32_t*)&h;
}

/* ------------------------------------------------------------------ */
/* pgemm: C[m][n] = sum_k A[m][k]*B[k][n] + bias[n]                    */
/*   bf16 hi/lo 3-pass tensor-core GEMM, tile 64 rows x 32 cols,       */
/*   K looped in-CTA in chunks of 64 (no split-K).                     */
/*   A row-major (lda), B row-major (ldb), C row-major (ldc).          */
/*   grid (N/32, M/64), 128 threads.                                   */
/* ------------------------------------------------------------------ */
#define PG_AH 0
#define PG_AL 8192
#define PG_BH 16384
#define PG_BL 20480

__global__ __launch_bounds__(128, 2) void pgemm(
    const float* __restrict__ A, int lda,
    const float* __restrict__ B, int ldb,
    float* __restrict__ C, int ldc,
    const float* __restrict__ bias)
{
    __shared__ char smem[24576];
    const uint32_t sb = (uint32_t)__cvta_generic_to_shared(smem);
    const int tid  = threadIdx.x;
    const int lane = tid & 31, wid = tid >> 5;
    const int n0   = blockIdx.x * 32, m0 = blockIdx.y * 64;
    const int gq   = lane >> 2, tig = lane & 3;
    const int wr0  = wid * 16;

    const int jr  = tid >> 1;            /* 0..63 (A row / B k-row)   */
    const int e0a = (tid & 1) * 32;      /* A k-half                  */
    const int n0h = (tid & 1) * 16;      /* B n-half                  */

    float sacc[4][4];
#pragma unroll
    for (int n = 0; n < 4; n++)
#pragma unroll
        for (int c = 0; c < 4; c++) sacc[n][c] = 0.f;

    for (int k0 = 0; k0 < DIM; k0 += 64) {
        /* ---- A chunk 64x64 -> smem hi/lo (128B rows, swizzled) ---- */
        {
            const float* ap = &A[(size_t)(m0 + jr) * lda + k0 + e0a];
#pragma unroll
            for (int i = 0; i < 8; i++) {
                float4 a4 = *(const float4*)&ap[4 * i];
                uint32_t off = (uint32_t)(jr * 128)
                    + (((uint32_t)(2 * (e0a + 4 * i))) ^ (((uint32_t)jr & 7u) << 4));
                uint32_t l01, l23;
                uint32_t h01 = hipair(a4.x, a4.y, l01);
                uint32_t h23 = hipair(a4.z, a4.w, l23);
                *(uint2*)(smem + PG_AH + off) = make_uint2(h01, h23);
                *(uint2*)(smem + PG_AL + off) = make_uint2(l01, l23);
            }
        }
        /* ---- B chunk 64k x 32n -> smem transposed (rows = n) ---- */
        {
            const float* bp = &B[(size_t)(k0 + jr) * ldb + n0 + n0h];
#pragma unroll
            for (int i = 0; i < 4; i++) {
                float4 b4 = *(const float4*)&bp[4 * i];
#pragma unroll
                for (int u = 0; u < 4; u++) {
                    float f = (u == 0) ? b4.x : (u == 1) ? b4.y : (u == 2) ? b4.z : b4.w;
                    int n = n0h + 4 * i + u;
                    uint32_t off = (uint32_t)(n * 128)
                        + (((uint32_t)(2 * jr)) ^ (((uint32_t)n & 7u) << 4));
                    __nv_bfloat16 h = __float2bfloat16(f);
                    *(__nv_bfloat16*)(smem + PG_BH + off) = h;
                    *(__nv_bfloat16*)(smem + PG_BL + off) =
                        __float2bfloat16(f - __bfloat162float(h));
                }
            }
        }
        __syncthreads();

        /* ---- 3-pass MMA: Ah*Bh + Al*Bh + Ah*Bl ---- */
#pragma unroll
        for (int e = 0; e < 4; e++) {
            const uint32_t cb = (uint32_t)(e * 32);
            const int arow = wr0 + (lane & 15);
            uint32_t aoff = (uint32_t)(arow * 128)
                + ((cb + (uint32_t)((lane >> 4) << 4)) ^ (((uint32_t)arow & 7u) << 4));
            uint32_t ah[4], al[4];
            ldsm_x4(ah, sb + PG_AH + aoff);
            ldsm_x4(al, sb + PG_AL + aoff);
#pragma unroll
            for (int np = 0; np < 2; np++) {
                const int br = np * 16 + ((lane >> 4) & 1) * 8 + (lane & 7);
                uint32_t boff = (uint32_t)(br * 128)
                    + (((uint32_t)(cb + ((lane >> 3) & 1) * 16)) ^ (((uint32_t)br & 7u) << 4));
                uint32_t bh[4], bl[4];
                ldsm_x4(bh, sb + PG_BH + boff);
                ldsm_x4(bl, sb + PG_BL + boff);
                mma_bf16(sacc[2*np],   ah, bh[0], bh[1]);
                mma_bf16(sacc[2*np+1], ah, bh[2], bh[3]);
                mma_bf16(sacc[2*np],   al, bh[0], bh[1]);
                mma_bf16(sacc[2*np+1], al, bh[2], bh[3]);
                mma_bf16(sacc[2*np],   ah, bl[0], bl[1]);
                mma_bf16(sacc[2*np+1], ah, bl[2], bl[3]);
            }
        }
        __syncthreads();
    }

    /* ---- epilogue: bias + write ---- */
#pragma unroll
    for (int n = 0; n < 4; n++) {
        int col = n0 + n * 8 + 2 * tig;
        float2 bb = *(const float2*)&bias[col];
        int r0 = m0 + wr0 + gq;
        *(float2*)&C[(size_t)r0 * ldc + col] =
            make_float2(sacc[n][0] + bb.x, sacc[n][1] + bb.y);
        *(float2*)&C[(size_t)(r0 + 8) * ldc + col] =
            make_float2(sacc[n][2] + bb.x, sacc[n][3] + bb.y);
    }
}

/* ------------------------------------------------------------------ */
/* attn7: profiled attn6 structure, Q/tail read g_qkv directly          */
/*  grid (ASPL9, B), 128 threads, 2 CTAs/SM, smem 96KB                 */
/*  S = QhKh+QlKh+QhKl ; O = PhVh+PlVh+PhVl                            */
/* ------------------------------------------------------------------ */
#define OQH7 0
#define OQL7 16384
#define OKH7 32768
#define OKL7 49152
#define OVH7 65536
#define OVL7 81920
#define SMEM7 98304

__global__ __launch_bounds__(128, 2) void attn7(
    const float* __restrict__ bias,
    const float* __restrict__ cache_k,
    const float* __restrict__ cache_v)
{
    extern __shared__ char smem[];
    const uint32_t sb = (uint32_t)__cvta_generic_to_shared(smem);
    const int tid  = threadIdx.x;
    const int lane = tid & 31, wid = tid >> 5;
    const int s    = blockIdx.x, b = blockIdx.y;
    const int gq   = lane >> 2, tig = lane & 3;
    const int wr0  = wid * 16;

    const int jr = tid >> 1;             /* row handled by this thread (0..63) */
    const int e0 = (tid & 1) * 64;       /* fp32-column half                   */
    const uint32_t rb = (uint32_t)(jr * 256);
    const uint32_t sx = ((uint32_t)jr & 7u) << 4;

    /* ---- Q -> smem (bf16 hi/lo, SCALE folded) ---- */
    {
        const float* qp = &g_qkv[(size_t)(b * QL + (jr & 3)) * NQKV + (jr >> 2) * HD + e0];
#pragma unroll
        for (int i = 0; i < 16; i++) {
            float4 q4 = *(const float4*)&qp[4 * i];
            q4.x *= SCALE; q4.y *= SCALE; q4.z *= SCALE; q4.w *= SCALE;
            uint32_t off = rb + (((uint32_t)(2 * (e0 + 4 * i))) ^ sx);
            uint32_t l01, l23;
            uint32_t h01 = hipair(q4.x, q4.y, l01);
            uint32_t h23 = hipair(q4.z, q4.w, l23);
            *(uint2*)(smem + OQH7 + off) = make_uint2(h01, h23);
            *(uint2*)(smem + OQL7 + off) = make_uint2(l01, l23);
        }
    }

    float oacc[16][4];
#pragma unroll
    for (int n = 0; n < 16; n++)
#pragma unroll
        for (int c = 0; c < 4; c++) oacc[n][c] = 0.f;
    float lacc0 = 0.f, lacc1 = 0.f;

    const size_t brow0 = ((size_t)b * 64 + wr0 + gq) * KVL;

    /* balanced tile range: tiles [128*s/9, 128*(s+1)/9) of 64 keys */
    const int t0 = (128 * s) / ASPL9;
    const int t1 = (128 * (s + 1)) / ASPL9;

    for (int t = t0; t < t1; t++) {
        const int kb = t * 64;

        /* ---- K,V tile -> smem hi/lo, rolling-cache patched ---- */
        {
            const int jg = kb + jr;
            const float *srck, *srcv;
            if (jg < KVL - QL) {
                const size_t off0 = ((size_t)b * KVL + jg + QL) * HD + e0;
                srck = cache_k + off0;
                srcv = cache_v + off0;
            } else {
                const size_t mrow = (size_t)(b * QL + (jg - (KVL - QL))) * NQKV;
                srck = g_qkv + mrow + 2048 + e0;
                srcv = g_qkv + mrow + 2176 + e0;
            }
#pragma unroll
            for (int i = 0; i < 16; i++) {
                float4 k4 = *(const float4*)&srck[4 * i];
                float4 v4 = *(const float4*)&srcv[4 * i];
                uint32_t off = rb + (((uint32_t)(2 * (e0 + 4 * i))) ^ sx);
                uint32_t kl01, kl23, vl01, vl23;
                uint32_t kh01 = hipair(k4.x, k4.y, kl01);
                uint32_t kh23 = hipair(k4.z, k4.w, kl23);
                uint32_t vh01 = hipair(v4.x, v4.y, vl01);
                uint32_t vh23 = hipair(v4.z, v4.w, vl23);
                *(uint2*)(smem + OKH7 + off) = make_uint2(kh01, kh23);
                *(uint2*)(smem + OKL7 + off) = make_uint2(kl01, kl23);
                *(uint2*)(smem + OVH7 + off) = make_uint2(vh01, vh23);
                *(uint2*)(smem + OVL7 + off) = make_uint2(vl01, vl23);
            }
        }
        __syncthreads();

        /* bias (LDG issued early, consumed after S-mma) */
        float2 bA[8], bB[8];
#pragma unroll
        for (int n = 0; n < 8; n++) {
            bA[n] = *(const float2*)&bias[brow0 + kb + n * 8 + 2 * tig];
            bB[n] = *(const float2*)&bias[brow0 + 8 * KVL + kb + n * 8 + 2 * tig];
        }

        float sacc[8][4];
#pragma unroll
        for (int n = 0; n < 8; n++)
#pragma unroll
            for (int c = 0; c < 4; c++) sacc[n][c] = 0.f;

        /* ---- S = Qh Kh + Ql Kh + Qh Kl ---- */
#pragma unroll
        for (int e = 0; e < 8; e++) {
            const uint32_t cb = (uint32_t)(e * 32);
            const int arow = wr0 + (lane & 15);
            uint32_t aoff = (uint32_t)(arow * 256)
                + ((cb + (uint32_t)((lane >> 4) << 4)) ^ (((uint32_t)arow & 7u) << 4));
            uint32_t aqh[4], aql[4];
            ldsm_x4(aqh, sb + OQH7 + aoff);
            ldsm_x4(aql, sb + OQL7 + aoff);
#pragma unroll
            for (int np = 0; np < 4; np++) {
                const int krow = np * 16 + ((lane >> 4) & 1) * 8 + (lane & 7);
                uint32_t koff = (uint32_t)(krow * 256)
                    + (((uint32_t)(cb + ((lane >> 3) & 1) * 16)) ^ (((uint32_t)krow & 7u) << 4));
                uint32_t bh[4], bl[4];
                ldsm_x4(bh, sb + OKH7 + koff);
                ldsm_x4(bl, sb + OKL7 + koff);
                mma_bf16(sacc[2*np],   aqh, bh[0], bh[1]);
                mma_bf16(sacc[2*np+1], aqh, bh[2], bh[3]);
                mma_bf16(sacc[2*np],   aql, bh[0], bh[1]);
                mma_bf16(sacc[2*np+1], aql, bh[2], bh[3]);
                mma_bf16(sacc[2*np],   aqh, bl[0], bl[1]);
                mma_bf16(sacc[2*np+1], aqh, bl[2], bl[3]);
            }
        }

        /* ---- softmax (fixed shift) + O += Ph Vh + Pl Vh + Ph Vl ---- */
#pragma unroll
        for (int kk = 0; kk < 4; kk++) {
            uint32_t pah[4], pal[4];
#pragma unroll
            for (int h = 0; h < 2; h++) {
                const int n = 2 * kk + h;
                float p0 = __expf(sacc[n][0] + bA[n].x - SMAX);
                float p1 = __expf(sacc[n][1] + bA[n].y - SMAX);
                float p2 = __expf(sacc[n][2] + bB[n].x - SMAX);
                float p3 = __expf(sacc[n][3] + bB[n].y - SMAX);
                lacc0 += p0 + p1;
                lacc1 += p2 + p3;
                pah[2*h]   = hipair(p0, p1, pal[2*h]);
                pah[2*h+1] = hipair(p2, p3, pal[2*h+1]);
            }
#pragma unroll
            for (int np = 0; np < 8; np++) {
                const int vrow = kk * 16 + ((lane >> 3) & 1) * 8 + (lane & 7);
                uint32_t voff = (uint32_t)(vrow * 256)
                    + (((uint32_t)(np * 32 + ((lane >> 4) & 1) * 16)) ^ (((uint32_t)vrow & 7u) << 4));
                uint32_t vh[4], vl[4];
                ldsm_x4t(vh, sb + OVH7 + voff);
                ldsm_x4t(vl, sb + OVL7 + voff);
                mma_bf16(oacc[2*np],   pah, vh[0], vh[1]);
                mma_bf16(oacc[2*np+1], pah, vh[2], vh[3]);
                mma_bf16(oacc[2*np],   pal, vh[0], vh[1]);
                mma_bf16(oacc[2*np+1], pal, vh[2], vh[3]);
                mma_bf16(oacc[2*np],   pah, vl[0], vl[1]);
                mma_bf16(oacc[2*np+1], pah, vl[2], vl[3]);
            }
        }
        __syncthreads();   /* done reading K/V before next tile's stores */
    }

    /* ---- epilogue: unnormalized partial O + row sums ---- */
    {
        const int row0 = b * 64 + wr0 + gq;
#pragma unroll
        for (int n = 0; n < 16; n++) {
            int col = n * 8 + 2 * tig;
            *(float2*)&g_po[((size_t)row0 * ASPL9 + s) * HD + col] =
                make_float2(oacc[n][0], oacc[n][1]);
            *(float2*)&g_po[((size_t)(row0 + 8) * ASPL9 + s) * HD + col] =
                make_float2(oacc[n][2], oacc[n][3]);
        }
        lacc0 += __shfl_xor_sync(0xffffffffu, lacc0, 1);
        lacc0 += __shfl_xor_sync(0xffffffffu, lacc0, 2);
        lacc1 += __shfl_xor_sync(0xffffffffu, lacc1, 1);
        lacc1 += __shfl_xor_sync(0xffffffffu, lacc1, 2);
        if (tig == 0) {
            g_pml[row0 * ASPL9 + s]       = lacc0;
            g_pml[(row0 + 8) * ASPL9 + s] = lacc1;
        }
    }
}

/* ------------------------------------------------------------------ */
/* Combine the 9 partial results: plain sum, divide by total l         */
/* ------------------------------------------------------------------ */
__global__ void combine9()
{
    int b = blockIdx.x, tid = threadIdx.x;   /* 128 threads */
    int r = tid >> 1, half = tid & 1;
    float lt = 0.f;
#pragma unroll
    for (int s = 0; s < ASPL9; s++) lt += g_pml[(b * 64 + r) * ASPL9 + s];
    float inv = 1.f / lt;
    int q = r & 3, h = r >> 2;
    float* dst = g_o + (size_t)(b * QL + q) * DIM + h * HD + half * 64;
    size_t pb = ((size_t)(b * 64 + r) * ASPL9) * HD + half * 64;
    for (int e = 0; e < 64; e += 4) {
        float4 acc = make_float4(0.f, 0.f, 0.f, 0.f);
#pragma unroll
        for (int s = 0; s < ASPL9; s++) {
            float4 v = *(const float4*)&g_po[pb + (size_t)s * HD + e];
            acc.x += v.x; acc.y += v.y; acc.z += v.z; acc.w += v.w;
        }
        acc.x *= inv; acc.y *= inv; acc.z *= inv; acc.w *= inv;
        *(float4*)&dst[e] = acc;
    }
}

/* ------------------------------------------------------------------ */
extern "C" void kernel_launch(void* const* d_in, const int* in_sizes, int n_in,
                              void* d_out, int out_size)
{
    const float* x         = (const float*)d_in[0];
    const float* attn_bias = (const float*)d_in[1];
    const float* cache_k   = (const float*)d_in[2];
    const float* cache_v   = (const float*)d_in[3];
    const float* wq        = (const float*)d_in[4];
    const float* bq        = (const float*)d_in[5];
    const float* wk        = (const float*)d_in[6];
    const float* bk        = (const float*)d_in[7];
    const float* wv        = (const float*)d_in[8];
    const float* bv        = (const float*)d_in[9];
    const float* wo        = (const float*)d_in[10];
    const float* bo        = (const float*)d_in[11];
    float*       out       = (float*)d_out;

    cudaFuncSetAttribute(attn7,
                         cudaFuncAttributeMaxDynamicSharedMemorySize, SMEM7);

    float* gqkv_ptr = nullptr;
    float* go_ptr   = nullptr;
    cudaGetSymbolAddress((void**)&gqkv_ptr, g_qkv);
    cudaGetSymbolAddress((void**)&go_ptr, g_o);

    /* 1) QKV projections (tensor-core, bias fused, full K in-CTA) */
    pgemm<<<dim3(64, 2), 128>>>(x, DIM, wq, 2048, gqkv_ptr,        NQKV, bq);
    pgemm<<<dim3(4, 2),  128>>>(x, DIM, wk, 128,  gqkv_ptr + 2048, NQKV, bk);
    pgemm<<<dim3(4, 2),  128>>>(x, DIM, wv, 128,  gqkv_ptr + 2176, NQKV, bv);

    /* 2) tensor-core flash attention, 9 balanced KV splits */
    attn7<<<dim3(ASPL9, B_), 128, SMEM7>>>(attn_bias, cache_k, cache_v);

    /* 3) combine splits */
    combine9<<<B_, 128>>>();

    /* 4) output projection (tensor-core, bias fused) */
    pgemm<<<dim3(64, 2), 128>>>(go_ptr, DIM, wo, DIM, out, DIM, bo);
}

// round 16
// speedup vs baseline: 1.0309x; 1.0309x over previous
#include <cuda_runtime.h>
#include <cuda_bf16.h>
#include <cstdint>

typedef unsigned long long u64;

#define B_      32
#define QL      4
#define DIM     2048
#define HEADS   16
#define HD      128
#define KVL     8192
#define M_      (B_*QL)
#define NQKV    2304
#define ASPL9   9                /* attention KV splits (288 CTAs ~ 2/SM)  */
#define SCALE   0.08838834764831845f
#define SMAX    16.0f

/* ------------------------------------------------------------------ */
__device__ float g_qkv[M_ * NQKV];                      /* q | k_new | v_new */
__device__ float g_po [(size_t)B_ * 64 * ASPL9 * HD];
__device__ float g_pml[B_ * 64 * ASPL9];
__device__ float g_o  [M_ * DIM];

/* ---------------- mma.sync helpers -------------------------------- */
__device__ __forceinline__ void ldsm_x4(uint32_t* a, uint32_t addr) {
    asm volatile("ldmatrix.sync.aligned.m8n8.x4.shared.b16 {%0,%1,%2,%3}, [%4];"
        : "=r"(a[0]), "=r"(a[1]), "=r"(a[2]), "=r"(a[3]) : "r"(addr));
}
__device__ __forceinline__ void ldsm_x4t(uint32_t* a, uint32_t addr) {
    asm volatile("ldmatrix.sync.aligned.m8n8.x4.trans.shared.b16 {%0,%1,%2,%3}, [%4];"
        : "=r"(a[0]), "=r"(a[1]), "=r"(a[2]), "=r"(a[3]) : "r"(addr));
}
__device__ __forceinline__ void mma_bf16(float* c, const uint32_t* a,
                                         uint32_t b0, uint32_t b1) {
    asm volatile("mma.sync.aligned.m16n8k16.row.col.f32.bf16.bf16.f32 "
        "{%0,%1,%2,%3}, {%4,%5,%6,%7}, {%8,%9}, {%0,%1,%2,%3};"
        : "+f"(c[0]), "+f"(c[1]), "+f"(c[2]), "+f"(c[3])
        : "r"(a[0]), "r"(a[1]), "r"(a[2]), "r"(a[3]), "r"(b0), "r"(b1));
}

__device__ __forceinline__ uint32_t bfpair(float a, float b) {
    __nv_bfloat162 t = __floats2bfloat162_rn(a, b);
    return *(uint32_t*)&t;
}
__device__ __forceinline__ uint32_t hipair(float a, float b, uint32_t& lo) {
    __nv_bfloat16 ha = __float2bfloat16(a), hb = __float2bfloat16(b);
    lo = bfpair(a - __bfloat162float(ha), b - __bfloat162float(hb));
    __nv_bfloat162 h; h.x = ha; h.y = hb;
    return *(uint32_t*)&h;
}

/* ------------------------------------------------------------------ */
/* pgemm2: C[m][n] = sum_k A[m][k]*B[k][n] + bias[n]                   */
/*   tile 64m x 32n, K looped in chunks of 64, register-prefetched.    */
/*   A stored m-major rows (like Q); B stored k-major rows consumed    */
/*   via ldsm.trans (the proven V pattern — contiguous stores).        */
/*   grid (N/32, M/64), 128 threads.                                   */
/* ------------------------------------------------------------------ */
#define P2_AH 0
#define P2_AL 8192
#define P2_BH 16384
#define P2_BL 24576
#define P2_SMEM 32768

__global__ __launch_bounds__(128, 2) void pgemm2(
    const float* __restrict__ A, int lda,
    const float* __restrict__ B, int ldb,
    float* __restrict__ C, int ldc,
    const float* __restrict__ bias)
{
    __shared__ char smem[P2_SMEM];
    const uint32_t sb = (uint32_t)__cvta_generic_to_shared(smem);
    const int tid  = threadIdx.x;
    const int lane = tid & 31, wid = tid >> 5;
    const int n0   = blockIdx.x * 32, m0 = blockIdx.y * 64;
    const int gq   = lane >> 2, tig = lane & 3;
    const int wr0  = wid * 16;

    /* loader maps */
    const int ar  = tid >> 1;            /* A row 0..63               */
    const int ac0 = (tid & 1) * 32;      /* A k-col half              */
    const int kr  = tid >> 1;            /* B k-row 0..63             */
    const int nc0 = (tid & 1) * 16;      /* B n-col half              */
    const uint32_t asx = ((uint32_t)ar & 7u) << 4;
    const uint32_t bsx = ((uint32_t)kr & 7u) << 4;

    float4 aprf[8], bprf[4];

    /* prologue: prefetch chunk 0 */
    {
        const float* ap = &A[(size_t)(m0 + ar) * lda + ac0];
#pragma unroll
        for (int i = 0; i < 8; i++) aprf[i] = *(const float4*)&ap[4 * i];
        const float* bp = &B[(size_t)kr * ldb + n0 + nc0];
#pragma unroll
        for (int i = 0; i < 4; i++) bprf[i] = *(const float4*)&bp[4 * i];
    }

    float sacc[4][4];
#pragma unroll
    for (int n = 0; n < 4; n++)
#pragma unroll
        for (int c = 0; c < 4; c++) sacc[n][c] = 0.f;

    const int nch = lda / 64;            /* K chunks (lda == K here)  */
    for (int ch = 0; ch < nch; ch++) {
        /* ---- convert + STS prefetched chunk ---- */
#pragma unroll
        for (int i = 0; i < 8; i++) {
            float4 a4 = aprf[i];
            uint32_t off = (uint32_t)(ar * 128) + (((uint32_t)(2 * (ac0 + 4 * i))) ^ asx);
            uint32_t l01, l23;
            uint32_t h01 = hipair(a4.x, a4.y, l01);
            uint32_t h23 = hipair(a4.z, a4.w, l23);
            *(uint2*)(smem + P2_AH + off) = make_uint2(h01, h23);
            *(uint2*)(smem + P2_AL + off) = make_uint2(l01, l23);
        }
#pragma unroll
        for (int i = 0; i < 4; i++) {
            float4 b4 = bprf[i];
            uint32_t off = (uint32_t)(kr * 128) + (((uint32_t)(2 * (nc0 + 4 * i))) ^ bsx);
            uint32_t l01, l23;
            uint32_t h01 = hipair(b4.x, b4.y, l01);
            uint32_t h23 = hipair(b4.z, b4.w, l23);
            *(uint2*)(smem + P2_BH + off) = make_uint2(h01, h23);
            *(uint2*)(smem + P2_BL + off) = make_uint2(l01, l23);
        }
        __syncthreads();

        /* ---- prefetch chunk ch+1 (LDG latency hides under MMA) ---- */
        if (ch + 1 < nch) {
            const int k0 = (ch + 1) * 64;
            const float* ap = &A[(size_t)(m0 + ar) * lda + k0 + ac0];
#pragma unroll
            for (int i = 0; i < 8; i++) aprf[i] = *(const float4*)&ap[4 * i];
            const float* bp = &B[(size_t)(k0 + kr) * ldb + n0 + nc0];
#pragma unroll
            for (int i = 0; i < 4; i++) bprf[i] = *(const float4*)&bp[4 * i];
        }

        /* ---- 3-pass MMA: Ah*Bh + Al*Bh + Ah*Bl ---- */
#pragma unroll
        for (int e = 0; e < 4; e++) {
            const uint32_t cb = (uint32_t)(e * 32);
            const int arow = wr0 + (lane & 15);
            uint32_t aoff = (uint32_t)(arow * 128)
                + ((cb + (uint32_t)((lane >> 4) << 4)) ^ (((uint32_t)arow & 7u) << 4));
            uint32_t ah[4], al[4];
            ldsm_x4(ah, sb + P2_AH + aoff);
            ldsm_x4(al, sb + P2_AL + aoff);
#pragma unroll
            for (int np = 0; np < 2; np++) {
                const int brow = e * 16 + ((lane >> 3) & 1) * 8 + (lane & 7);
                uint32_t boff = (uint32_t)(brow * 128)
                    + (((uint32_t)(np * 32 + ((lane >> 4) & 1) * 16)) ^ (((uint32_t)brow & 7u) << 4));
                uint32_t bh[4], bl[4];
                ldsm_x4t(bh, sb + P2_BH + boff);
                ldsm_x4t(bl, sb + P2_BL + boff);
                mma_bf16(sacc[2*np],   ah, bh[0], bh[1]);
                mma_bf16(sacc[2*np+1], ah, bh[2], bh[3]);
                mma_bf16(sacc[2*np],   al, bh[0], bh[1]);
                mma_bf16(sacc[2*np+1], al, bh[2], bh[3]);
                mma_bf16(sacc[2*np],   ah, bl[0], bl[1]);
                mma_bf16(sacc[2*np+1], ah, bl[2], bl[3]);
            }
        }
        __syncthreads();
    }

    /* ---- epilogue: bias + write ---- */
#pragma unroll
    for (int n = 0; n < 4; n++) {
        int col = n0 + n * 8 + 2 * tig;
        float2 bb = *(const float2*)&bias[col];
        int r0 = m0 + wr0 + gq;
        *(float2*)&C[(size_t)r0 * ldc + col] =
            make_float2(sacc[n][0] + bb.x, sacc[n][1] + bb.y);
        *(float2*)&C[(size_t)(r0 + 8) * ldc + col] =
            make_float2(sacc[n][2] + bb.x, sacc[n][3] + bb.y);
    }
}

/* ------------------------------------------------------------------ */
/* attn7 (unchanged from R15 — profiled at 156us)                      */
/* ------------------------------------------------------------------ */
#define OQH7 0
#define OQL7 16384
#define OKH7 32768
#define OKL7 49152
#define OVH7 65536
#define OVL7 81920
#define SMEM7 98304

__global__ __launch_bounds__(128, 2) void attn7(
    const float* __restrict__ bias,
    const float* __restrict__ cache_k,
    const float* __restrict__ cache_v)
{
    extern __shared__ char smem[];
    const uint32_t sb = (uint32_t)__cvta_generic_to_shared(smem);
    const int tid  = threadIdx.x;
    const int lane = tid & 31, wid = tid >> 5;
    const int s    = blockIdx.x, b = blockIdx.y;
    const int gq   = lane >> 2, tig = lane & 3;
    const int wr0  = wid * 16;

    const int jr = tid >> 1;
    const int e0 = (tid & 1) * 64;
    const uint32_t rb = (uint32_t)(jr * 256);
    const uint32_t sx = ((uint32_t)jr & 7u) << 4;

    /* ---- Q -> smem (bf16 hi/lo, SCALE folded) ---- */
    {
        const float* qp = &g_qkv[(size_t)(b * QL + (jr & 3)) * NQKV + (jr >> 2) * HD + e0];
#pragma unroll
        for (int i = 0; i < 16; i++) {
            float4 q4 = *(const float4*)&qp[4 * i];
            q4.x *= SCALE; q4.y *= SCALE; q4.z *= SCALE; q4.w *= SCALE;
            uint32_t off = rb + (((uint32_t)(2 * (e0 + 4 * i))) ^ sx);
            uint32_t l01, l23;
            uint32_t h01 = hipair(q4.x, q4.y, l01);
            uint32_t h23 = hipair(q4.z, q4.w, l23);
            *(uint2*)(smem + OQH7 + off) = make_uint2(h01, h23);
            *(uint2*)(smem + OQL7 + off) = make_uint2(l01, l23);
        }
    }

    float oacc[16][4];
#pragma unroll
    for (int n = 0; n < 16; n++)
#pragma unroll
        for (int c = 0; c < 4; c++) oacc[n][c] = 0.f;
    float lacc0 = 0.f, lacc1 = 0.f;

    const size_t brow0 = ((size_t)b * 64 + wr0 + gq) * KVL;

    const int t0 = (128 * s) / ASPL9;
    const int t1 = (128 * (s + 1)) / ASPL9;

    for (int t = t0; t < t1; t++) {
        const int kb = t * 64;

        {
            const int jg = kb + jr;
            const float *srck, *srcv;
            if (jg < KVL - QL) {
                const size_t off0 = ((size_t)b * KVL + jg + QL) * HD + e0;
                srck = cache_k + off0;
                srcv = cache_v + off0;
            } else {
                const size_t mrow = (size_t)(b * QL + (jg - (KVL - QL))) * NQKV;
                srck = g_qkv + mrow + 2048 + e0;
                srcv = g_qkv + mrow + 2176 + e0;
            }
#pragma unroll
            for (int i = 0; i < 16; i++) {
                float4 k4 = *(const float4*)&srck[4 * i];
                float4 v4 = *(const float4*)&srcv[4 * i];
                uint32_t off = rb + (((uint32_t)(2 * (e0 + 4 * i))) ^ sx);
                uint32_t kl01, kl23, vl01, vl23;
                uint32_t kh01 = hipair(k4.x, k4.y, kl01);
                uint32_t kh23 = hipair(k4.z, k4.w, kl23);
                uint32_t vh01 = hipair(v4.x, v4.y, vl01);
                uint32_t vh23 = hipair(v4.z, v4.w, vl23);
                *(uint2*)(smem + OKH7 + off) = make_uint2(kh01, kh23);
                *(uint2*)(smem + OKL7 + off) = make_uint2(kl01, kl23);
                *(uint2*)(smem + OVH7 + off) = make_uint2(vh01, vh23);
                *(uint2*)(smem + OVL7 + off) = make_uint2(vl01, vl23);
            }
        }
        __syncthreads();

        float2 bA[8], bB[8];
#pragma unroll
        for (int n = 0; n < 8; n++) {
            bA[n] = *(const float2*)&bias[brow0 + kb + n * 8 + 2 * tig];
            bB[n] = *(const float2*)&bias[brow0 + 8 * KVL + kb + n * 8 + 2 * tig];
        }

        float sacc[8][4];
#pragma unroll
        for (int n = 0; n < 8; n++)
#pragma unroll
            for (int c = 0; c < 4; c++) sacc[n][c] = 0.f;

#pragma unroll
        for (int e = 0; e < 8; e++) {
            const uint32_t cb = (uint32_t)(e * 32);
            const int arow = wr0 + (lane & 15);
            uint32_t aoff = (uint32_t)(arow * 256)
                + ((cb + (uint32_t)((lane >> 4) << 4)) ^ (((uint32_t)arow & 7u) << 4));
            uint32_t aqh[4], aql[4];
            ldsm_x4(aqh, sb + OQH7 + aoff);
            ldsm_x4(aql, sb + OQL7 + aoff);
#pragma unroll
            for (int np = 0; np < 4; np++) {
                const int krow = np * 16 + ((lane >> 4) & 1) * 8 + (lane & 7);
                uint32_t koff = (uint32_t)(krow * 256)
                    + (((uint32_t)(cb + ((lane >> 3) & 1) * 16)) ^ (((uint32_t)krow & 7u) << 4));
                uint32_t bh[4], bl[4];
                ldsm_x4(bh, sb + OKH7 + koff);
                ldsm_x4(bl, sb + OKL7 + koff);
                mma_bf16(sacc[2*np],   aqh, bh[0], bh[1]);
                mma_bf16(sacc[2*np+1], aqh, bh[2], bh[3]);
                mma_bf16(sacc[2*np],   aql, bh[0], bh[1]);
                mma_bf16(sacc[2*np+1], aql, bh[2], bh[3]);
                mma_bf16(sacc[2*np],   aqh, bl[0], bl[1]);
                mma_bf16(sacc[2*np+1], aqh, bl[2], bl[3]);
            }
        }

#pragma unroll
        for (int kk = 0; kk < 4; kk++) {
            uint32_t pah[4], pal[4];
#pragma unroll
            for (int h = 0; h < 2; h++) {
                const int n = 2 * kk + h;
                float p0 = __expf(sacc[n][0] + bA[n].x - SMAX);
                float p1 = __expf(sacc[n][1] + bA[n].y - SMAX);
                float p2 = __expf(sacc[n][2] + bB[n].x - SMAX);
                float p3 = __expf(sacc[n][3] + bB[n].y - SMAX);
                lacc0 += p0 + p1;
                lacc1 += p2 + p3;
                pah[2*h]   = hipair(p0, p1, pal[2*h]);
                pah[2*h+1] = hipair(p2, p3, pal[2*h+1]);
            }
#pragma unroll
            for (int np = 0; np < 8; np++) {
                const int vrow = kk * 16 + ((lane >> 3) & 1) * 8 + (lane & 7);
                uint32_t voff = (uint32_t)(vrow * 256)
                    + (((uint32_t)(np * 32 + ((lane >> 4) & 1) * 16)) ^ (((uint32_t)vrow & 7u) << 4));
                uint32_t vh[4], vl[4];
                ldsm_x4t(vh, sb + OVH7 + voff);
                ldsm_x4t(vl, sb + OVL7 + voff);
                mma_bf16(oacc[2*np],   pah, vh[0], vh[1]);
                mma_bf16(oacc[2*np+1], pah, vh[2], vh[3]);
                mma_bf16(oacc[2*np],   pal, vh[0], vh[1]);
                mma_bf16(oacc[2*np+1], pal, vh[2], vh[3]);
                mma_bf16(oacc[2*np],   pah, vl[0], vl[1]);
                mma_bf16(oacc[2*np+1], pah, vl[2], vl[3]);
            }
        }
        __syncthreads();
    }

    {
        const int row0 = b * 64 + wr0 + gq;
#pragma unroll
        for (int n = 0; n < 16; n++) {
            int col = n * 8 + 2 * tig;
            *(float2*)&g_po[((size_t)row0 * ASPL9 + s) * HD + col] =
                make_float2(oacc[n][0], oacc[n][1]);
            *(float2*)&g_po[((size_t)(row0 + 8) * ASPL9 + s) * HD + col] =
                make_float2(oacc[n][2], oacc[n][3]);
        }
        lacc0 += __shfl_xor_sync(0xffffffffu, lacc0, 1);
        lacc0 += __shfl_xor_sync(0xffffffffu, lacc0, 2);
        lacc1 += __shfl_xor_sync(0xffffffffu, lacc1, 1);
        lacc1 += __shfl_xor_sync(0xffffffffu, lacc1, 2);
        if (tig == 0) {
            g_pml[row0 * ASPL9 + s]       = lacc0;
            g_pml[(row0 + 8) * ASPL9 + s] = lacc1;
        }
    }
}

/* ------------------------------------------------------------------ */
__global__ void combine9()
{
    int b = blockIdx.x, tid = threadIdx.x;   /* 128 threads */
    int r = tid >> 1, half = tid & 1;
    float lt = 0.f;
#pragma unroll
    for (int s = 0; s < ASPL9; s++) lt += g_pml[(b * 64 + r) * ASPL9 + s];
    float inv = 1.f / lt;
    int q = r & 3, h = r >> 2;
    float* dst = g_o + (size_t)(b * QL + q) * DIM + h * HD + half * 64;
    size_t pb = ((size_t)(b * 64 + r) * ASPL9) * HD + half * 64;
    for (int e = 0; e < 64; e += 4) {
        float4 acc = make_float4(0.f, 0.f, 0.f, 0.f);
#pragma unroll
        for (int s = 0; s < ASPL9; s++) {
            float4 v = *(const float4*)&g_po[pb + (size_t)s * HD + e];
            acc.x += v.x; acc.y += v.y; acc.z += v.z; acc.w += v.w;
        }
        acc.x *= inv; acc.y *= inv; acc.z *= inv; acc.w *= inv;
        *(float4*)&dst[e] = acc;
    }
}

/* ------------------------------------------------------------------ */
extern "C" void kernel_launch(void* const* d_in, const int* in_sizes, int n_in,
                              void* d_out, int out_size)
{
    const float* x         = (const float*)d_in[0];
    const float* attn_bias = (const float*)d_in[1];
    const float* cache_k   = (const float*)d_in[2];
    const float* cache_v   = (const float*)d_in[3];
    const float* wq        = (const float*)d_in[4];
    const float* bq        = (const float*)d_in[5];
    const float* wk        = (const float*)d_in[6];
    const float* bk        = (const float*)d_in[7];
    const float* wv        = (const float*)d_in[8];
    const float* bv        = (const float*)d_in[9];
    const float* wo        = (const float*)d_in[10];
    const float* bo        = (const float*)d_in[11];
    float*       out       = (float*)d_out;

    cudaFuncSetAttribute(attn7,
                         cudaFuncAttributeMaxDynamicSharedMemorySize, SMEM7);

    float* gqkv_ptr = nullptr;
    float* go_ptr   = nullptr;
    cudaGetSymbolAddress((void**)&gqkv_ptr, g_qkv);
    cudaGetSymbolAddress((void**)&go_ptr, g_o);

    /* 1) QKV projections (tensor-core, register-prefetched, bias fused) */
    pgemm2<<<dim3(64, 2), 128>>>(x, DIM, wq, 2048, gqkv_ptr,        NQKV, bq);
    pgemm2<<<dim3(4, 2),  128>>>(x, DIM, wk, 128,  gqkv_ptr + 2048, NQKV, bk);
    pgemm2<<<dim3(4, 2),  128>>>(x, DIM, wv, 128,  gqkv_ptr + 2176, NQKV, bv);

    /* 2) tensor-core flash attention, 9 balanced KV splits */
    attn7<<<dim3(ASPL9, B_), 128, SMEM7>>>(attn_bias, cache_k, cache_v);

    /* 3) combine splits */
    combine9<<<B_, 128>>>();

    /* 4) output projection (tensor-core, bias fused) */
    pgemm2<<<dim3(64, 2), 128>>>(go_ptr, DIM, wo, DIM, out, DIM, bo);
}

// round 17
// speedup vs baseline: 1.4006x; 1.3586x over previous
#include <cuda_runtime.h>
#include <cuda_bf16.h>
#include <cstdint>

typedef unsigned long long u64;

#define B_      32
#define QL      4
#define DIM     2048
#define HEADS   16
#define HD      128
#define KVL     8192
#define M_      (B_*QL)
#define NQKV    2304
#define ASPL9   9                /* attention KV splits */
#define KSPL    4                /* projection K splits */
#define SCALE   0.08838834764831845f
#define SMAX    16.0f

/* ------------------------------------------------------------------ */
__device__ float g_part[KSPL * M_ * NQKV];              /* projection partials */
__device__ float g_qkv[M_ * NQKV];                      /* q | k_new | v_new   */
__device__ float g_po [(size_t)B_ * 64 * ASPL9 * HD];
__device__ float g_pml[B_ * 64 * ASPL9];
__device__ float g_o  [M_ * DIM];

/* ---------------- mma.sync helpers -------------------------------- */
__device__ __forceinline__ void ldsm_x4(uint32_t* a, uint32_t addr) {
    asm volatile("ldmatrix.sync.aligned.m8n8.x4.shared.b16 {%0,%1,%2,%3}, [%4];"
        : "=r"(a[0]), "=r"(a[1]), "=r"(a[2]), "=r"(a[3]) : "r"(addr));
}
__device__ __forceinline__ void ldsm_x4t(uint32_t* a, uint32_t addr) {
    asm volatile("ldmatrix.sync.aligned.m8n8.x4.trans.shared.b16 {%0,%1,%2,%3}, [%4];"
        : "=r"(a[0]), "=r"(a[1]), "=r"(a[2]), "=r"(a[3]) : "r"(addr));
}
__device__ __forceinline__ void mma_bf16(float* c, const uint32_t* a,
                                         uint32_t b0, uint32_t b1) {
    asm volatile("mma.sync.aligned.m16n8k16.row.col.f32.bf16.bf16.f32 "
        "{%0,%1,%2,%3}, {%4,%5,%6,%7}, {%8,%9}, {%0,%1,%2,%3};"
        : "+f"(c[0]), "+f"(c[1]), "+f"(c[2]), "+f"(c[3])
        : "r"(a[0]), "r"(a[1]), "r"(a[2]), "r"(a[3]), "r"(b0), "r"(b1));
}

__device__ __forceinline__ uint32_t bfpair(float a, float b) {
    __nv_bfloat162 t = __floats2bfloat162_rn(a, b);
    return *(uint32_t*)&t;
}
__device__ __forceinline__ uint32_t hipair(float a, float b, uint32_t& lo) {
    __nv_bfloat16 ha = __float2bfloat16(a), hb = __float2bfloat16(b);
    lo = bfpair(a - __bfloat162float(ha), b - __bfloat162float(hb));
    __nv_bfloat162 h; h.x = ha; h.y = hb;
    return *(uint32_t*)&h;
}

/* ------------------------------------------------------------------ */
/* pgemm3: partial[z][m][ncol0+n] = sum_{k in z-chunk} A[m][k]B[k][n]  */
/*   tensor-core hi/lo 3-pass, tile 64m x 32n, K split over blockIdx.z */
/*   (KSPL chunks of DIM/KSPL, register-prefetched 64k sub-chunks).    */
/*   grid (N/32, 2, KSPL), 128 threads.                                */
/* ------------------------------------------------------------------ */
#define P2_AH 0
#define P2_AL 8192
#define P2_BH 16384
#define P2_BL 24576

__global__ __launch_bounds__(128) void pgemm3(
    const float* __restrict__ A,
    const float* __restrict__ B, int ldb,
    int ncol0)
{
    __shared__ char smem[32768];
    const uint32_t sb = (uint32_t)__cvta_generic_to_shared(smem);
    const int tid  = threadIdx.x;
    const int lane = tid & 31, wid = tid >> 5;
    const int n0   = blockIdx.x * 32, m0 = blockIdx.y * 64;
    const int z    = blockIdx.z;
    const int gq   = lane >> 2, tig = lane & 3;
    const int wr0  = wid * 16;

    const int ar  = tid >> 1;            /* A row 0..63               */
    const int ac0 = (tid & 1) * 32;      /* A k-col half              */
    const int kr  = tid >> 1;            /* B k-row 0..63             */
    const int nc0 = (tid & 1) * 16;      /* B n-col half              */
    const uint32_t asx = ((uint32_t)ar & 7u) << 4;
    const uint32_t bsx = ((uint32_t)kr & 7u) << 4;

    const int kbase = z * (DIM / KSPL);
    const int nch   = (DIM / KSPL) / 64;   /* 8 */

    float4 aprf[8], bprf[4];
    {
        const float* ap = &A[(size_t)(m0 + ar) * DIM + kbase + ac0];
#pragma unroll
        for (int i = 0; i < 8; i++) aprf[i] = *(const float4*)&ap[4 * i];
        const float* bp = &B[(size_t)(kbase + kr) * ldb + n0 + nc0];
#pragma unroll
        for (int i = 0; i < 4; i++) bprf[i] = *(const float4*)&bp[4 * i];
    }

    float sacc[4][4];
#pragma unroll
    for (int n = 0; n < 4; n++)
#pragma unroll
        for (int c = 0; c < 4; c++) sacc[n][c] = 0.f;

    for (int ch = 0; ch < nch; ch++) {
        /* convert + STS prefetched chunk */
#pragma unroll
        for (int i = 0; i < 8; i++) {
            float4 a4 = aprf[i];
            uint32_t off = (uint32_t)(ar * 128) + (((uint32_t)(2 * (ac0 + 4 * i))) ^ asx);
            uint32_t l01, l23;
            uint32_t h01 = hipair(a4.x, a4.y, l01);
            uint32_t h23 = hipair(a4.z, a4.w, l23);
            *(uint2*)(smem + P2_AH + off) = make_uint2(h01, h23);
            *(uint2*)(smem + P2_AL + off) = make_uint2(l01, l23);
        }
#pragma unroll
        for (int i = 0; i < 4; i++) {
            float4 b4 = bprf[i];
            uint32_t off = (uint32_t)(kr * 128) + (((uint32_t)(2 * (nc0 + 4 * i))) ^ bsx);
            uint32_t l01, l23;
            uint32_t h01 = hipair(b4.x, b4.y, l01);
            uint32_t h23 = hipair(b4.z, b4.w, l23);
            *(uint2*)(smem + P2_BH + off) = make_uint2(h01, h23);
            *(uint2*)(smem + P2_BL + off) = make_uint2(l01, l23);
        }
        __syncthreads();

        /* prefetch next sub-chunk */
        if (ch + 1 < nch) {
            const int k0 = kbase + (ch + 1) * 64;
            const float* ap = &A[(size_t)(m0 + ar) * DIM + k0 + ac0];
#pragma unroll
            for (int i = 0; i < 8; i++) aprf[i] = *(const float4*)&ap[4 * i];
            const float* bp = &B[(size_t)(k0 + kr) * ldb + n0 + nc0];
#pragma unroll
            for (int i = 0; i < 4; i++) bprf[i] = *(const float4*)&bp[4 * i];
        }

        /* 3-pass MMA: Ah*Bh + Al*Bh + Ah*Bl */
#pragma unroll
        for (int e = 0; e < 4; e++) {
            const uint32_t cb = (uint32_t)(e * 32);
            const int arow = wr0 + (lane & 15);
            uint32_t aoff = (uint32_t)(arow * 128)
                + ((cb + (uint32_t)((lane >> 4) << 4)) ^ (((uint32_t)arow & 7u) << 4));
            uint32_t ah[4], al[4];
            ldsm_x4(ah, sb + P2_AH + aoff);
            ldsm_x4(al, sb + P2_AL + aoff);
#pragma unroll
            for (int np = 0; np < 2; np++) {
                const int brow = e * 16 + ((lane >> 3) & 1) * 8 + (lane & 7);
                uint32_t boff = (uint32_t)(brow * 128)
                    + (((uint32_t)(np * 32 + ((lane >> 4) & 1) * 16)) ^ (((uint32_t)brow & 7u) << 4));
                uint32_t bh[4], bl[4];
                ldsm_x4t(bh, sb + P2_BH + boff);
                ldsm_x4t(bl, sb + P2_BL + boff);
                mma_bf16(sacc[2*np],   ah, bh[0], bh[1]);
                mma_bf16(sacc[2*np+1], ah, bh[2], bh[3]);
                mma_bf16(sacc[2*np],   al, bh[0], bh[1]);
                mma_bf16(sacc[2*np+1], al, bh[2], bh[3]);
                mma_bf16(sacc[2*np],   ah, bl[0], bl[1]);
                mma_bf16(sacc[2*np+1], ah, bl[2], bl[3]);
            }
        }
        __syncthreads();
    }

    /* epilogue: write partials (no bias) */
    float* dst = g_part + (size_t)z * (M_ * NQKV);
#pragma unroll
    for (int n = 0; n < 4; n++) {
        int col = ncol0 + n0 + n * 8 + 2 * tig;
        int r0 = m0 + wr0 + gq;
        *(float2*)&dst[(size_t)r0 * NQKV + col] =
            make_float2(sacc[n][0], sacc[n][1]);
        *(float2*)&dst[(size_t)(r0 + 8) * NQKV + col] =
            make_float2(sacc[n][2], sacc[n][3]);
    }
}

/* ------------------------------------------------------------------ */
/* Reduce projection partials + biases -> g_qkv                        */
/* ------------------------------------------------------------------ */
__global__ void reduce_qkv4(const float* __restrict__ bq,
                            const float* __restrict__ bk,
                            const float* __restrict__ bv)
{
    int idx = blockIdx.x * 256 + threadIdx.x;
    if (idx >= M_ * NQKV / 4) return;
    int m = idx / (NQKV / 4);
    int n = (idx % (NQKV / 4)) * 4;
    float4 s = make_float4(0.f, 0.f, 0.f, 0.f);
#pragma unroll
    for (int z = 0; z < KSPL; z++) {
        float4 v = *(const float4*)&g_part[(size_t)z * (M_ * NQKV) + (size_t)m * NQKV + n];
        s.x += v.x; s.y += v.y; s.z += v.z; s.w += v.w;
    }
    float4 bb;
    if (n < 2048)       bb = *(const float4*)&bq[n];
    else if (n < 2176)  bb = *(const float4*)&bk[n - 2048];
    else                bb = *(const float4*)&bv[n - 2176];
    s.x += bb.x; s.y += bb.y; s.z += bb.z; s.w += bb.w;
    *(float4*)&g_qkv[(size_t)m * NQKV + n] = s;
}

/* ------------------------------------------------------------------ */
/* Reduce output-projection partials + bo -> out                       */
/* ------------------------------------------------------------------ */
__global__ void reduce_out4(const float* __restrict__ bo, float* __restrict__ out)
{
    int idx = blockIdx.x * 256 + threadIdx.x;   /* 128*2048/4 = 65536 */
    int m = idx >> 9;
    int n = (idx & 511) << 2;
    float4 s = *(const float4*)&bo[n];
#pragma unroll
    for (int z = 0; z < KSPL; z++) {
        float4 v = *(const float4*)&g_part[(size_t)z * (M_ * NQKV) + (size_t)m * NQKV + n];
        s.x += v.x; s.y += v.y; s.z += v.z; s.w += v.w;
    }
    *(float4*)&out[(size_t)m * DIM + n] = s;
}

/* ------------------------------------------------------------------ */
/* attn7 (unchanged — profiled at 156-158us)                           */
/* ------------------------------------------------------------------ */
#define OQH7 0
#define OQL7 16384
#define OKH7 32768
#define OKL7 49152
#define OVH7 65536
#define OVL7 81920
#define SMEM7 98304

__global__ __launch_bounds__(128, 2) void attn7(
    const float* __restrict__ bias,
    const float* __restrict__ cache_k,
    const float* __restrict__ cache_v)
{
    extern __shared__ char smem[];
    const uint32_t sb = (uint32_t)__cvta_generic_to_shared(smem);
    const int tid  = threadIdx.x;
    const int lane = tid & 31, wid = tid >> 5;
    const int s    = blockIdx.x, b = blockIdx.y;
    const int gq   = lane >> 2, tig = lane & 3;
    const int wr0  = wid * 16;

    const int jr = tid >> 1;
    const int e0 = (tid & 1) * 64;
    const uint32_t rb = (uint32_t)(jr * 256);
    const uint32_t sx = ((uint32_t)jr & 7u) << 4;

    {
        const float* qp = &g_qkv[(size_t)(b * QL + (jr & 3)) * NQKV + (jr >> 2) * HD + e0];
#pragma unroll
        for (int i = 0; i < 16; i++) {
            float4 q4 = *(const float4*)&qp[4 * i];
            q4.x *= SCALE; q4.y *= SCALE; q4.z *= SCALE; q4.w *= SCALE;
            uint32_t off = rb + (((uint32_t)(2 * (e0 + 4 * i))) ^ sx);
            uint32_t l01, l23;
            uint32_t h01 = hipair(q4.x, q4.y, l01);
            uint32_t h23 = hipair(q4.z, q4.w, l23);
            *(uint2*)(smem + OQH7 + off) = make_uint2(h01, h23);
            *(uint2*)(smem + OQL7 + off) = make_uint2(l01, l23);
        }
    }

    float oacc[16][4];
#pragma unroll
    for (int n = 0; n < 16; n++)
#pragma unroll
        for (int c = 0; c < 4; c++) oacc[n][c] = 0.f;
    float lacc0 = 0.f, lacc1 = 0.f;

    const size_t brow0 = ((size_t)b * 64 + wr0 + gq) * KVL;

    const int t0 = (128 * s) / ASPL9;
    const int t1 = (128 * (s + 1)) / ASPL9;

    for (int t = t0; t < t1; t++) {
        const int kb = t * 64;

        {
            const int jg = kb + jr;
            const float *srck, *srcv;
            if (jg < KVL - QL) {
                const size_t off0 = ((size_t)b * KVL + jg + QL) * HD + e0;
                srck = cache_k + off0;
                srcv = cache_v + off0;
            } else {
                const size_t mrow = (size_t)(b * QL + (jg - (KVL - QL))) * NQKV;
                srck = g_qkv + mrow + 2048 + e0;
                srcv = g_qkv + mrow + 2176 + e0;
            }
#pragma unroll
            for (int i = 0; i < 16; i++) {
                float4 k4 = *(const float4*)&srck[4 * i];
                float4 v4 = *(const float4*)&srcv[4 * i];
                uint32_t off = rb + (((uint32_t)(2 * (e0 + 4 * i))) ^ sx);
                uint32_t kl01, kl23, vl01, vl23;
                uint32_t kh01 = hipair(k4.x, k4.y, kl01);
                uint32_t kh23 = hipair(k4.z, k4.w, kl23);
                uint32_t vh01 = hipair(v4.x, v4.y, vl01);
                uint32_t vh23 = hipair(v4.z, v4.w, vl23);
                *(uint2*)(smem + OKH7 + off) = make_uint2(kh01, kh23);
                *(uint2*)(smem + OKL7 + off) = make_uint2(kl01, kl23);
                *(uint2*)(smem + OVH7 + off) = make_uint2(vh01, vh23);
                *(uint2*)(smem + OVL7 + off) = make_uint2(vl01, vl23);
            }
        }
        __syncthreads();

        float2 bA[8], bB[8];
#pragma unroll
        for (int n = 0; n < 8; n++) {
            bA[n] = *(const float2*)&bias[brow0 + kb + n * 8 + 2 * tig];
            bB[n] = *(const float2*)&bias[brow0 + 8 * KVL + kb + n * 8 + 2 * tig];
        }

        float sacc[8][4];
#pragma unroll
        for (int n = 0; n < 8; n++)
#pragma unroll
            for (int c = 0; c < 4; c++) sacc[n][c] = 0.f;

#pragma unroll
        for (int e = 0; e < 8; e++) {
            const uint32_t cb = (uint32_t)(e * 32);
            const int arow = wr0 + (lane & 15);
            uint32_t aoff = (uint32_t)(arow * 256)
                + ((cb + (uint32_t)((lane >> 4) << 4)) ^ (((uint32_t)arow & 7u) << 4));
            uint32_t aqh[4], aql[4];
            ldsm_x4(aqh, sb + OQH7 + aoff);
            ldsm_x4(aql, sb + OQL7 + aoff);
#pragma unroll
            for (int np = 0; np < 4; np++) {
                const int krow = np * 16 + ((lane >> 4) & 1) * 8 + (lane & 7);
                uint32_t koff = (uint32_t)(krow * 256)
                    + (((uint32_t)(cb + ((lane >> 3) & 1) * 16)) ^ (((uint32_t)krow & 7u) << 4));
                uint32_t bh[4], bl[4];
                ldsm_x4(bh, sb + OKH7 + koff);
                ldsm_x4(bl, sb + OKL7 + koff);
                mma_bf16(sacc[2*np],   aqh, bh[0], bh[1]);
                mma_bf16(sacc[2*np+1], aqh, bh[2], bh[3]);
                mma_bf16(sacc[2*np],   aql, bh[0], bh[1]);
                mma_bf16(sacc[2*np+1], aql, bh[2], bh[3]);
                mma_bf16(sacc[2*np],   aqh, bl[0], bl[1]);
                mma_bf16(sacc[2*np+1], aqh, bl[2], bl[3]);
            }
        }

#pragma unroll
        for (int kk = 0; kk < 4; kk++) {
            uint32_t pah[4], pal[4];
#pragma unroll
            for (int h = 0; h < 2; h++) {
                const int n = 2 * kk + h;
                float p0 = __expf(sacc[n][0] + bA[n].x - SMAX);
                float p1 = __expf(sacc[n][1] + bA[n].y - SMAX);
                float p2 = __expf(sacc[n][2] + bB[n].x - SMAX);
                float p3 = __expf(sacc[n][3] + bB[n].y - SMAX);
                lacc0 += p0 + p1;
                lacc1 += p2 + p3;
                pah[2*h]   = hipair(p0, p1, pal[2*h]);
                pah[2*h+1] = hipair(p2, p3, pal[2*h+1]);
            }
#pragma unroll
            for (int np = 0; np < 8; np++) {
                const int vrow = kk * 16 + ((lane >> 3) & 1) * 8 + (lane & 7);
                uint32_t voff = (uint32_t)(vrow * 256)
                    + (((uint32_t)(np * 32 + ((lane >> 4) & 1) * 16)) ^ (((uint32_t)vrow & 7u) << 4));
                uint32_t vh[4], vl[4];
                ldsm_x4t(vh, sb + OVH7 + voff);
                ldsm_x4t(vl, sb + OVL7 + voff);
                mma_bf16(oacc[2*np],   pah, vh[0], vh[1]);
                mma_bf16(oacc[2*np+1], pah, vh[2], vh[3]);
                mma_bf16(oacc[2*np],   pal, vh[0], vh[1]);
                mma_bf16(oacc[2*np+1], pal, vh[2], vh[3]);
                mma_bf16(oacc[2*np],   pah, vl[0], vl[1]);
                mma_bf16(oacc[2*np+1], pah, vl[2], vl[3]);
            }
        }
        __syncthreads();
    }

    {
        const int row0 = b * 64 + wr0 + gq;
#pragma unroll
        for (int n = 0; n < 16; n++) {
            int col = n * 8 + 2 * tig;
            *(float2*)&g_po[((size_t)row0 * ASPL9 + s) * HD + col] =
                make_float2(oacc[n][0], oacc[n][1]);
            *(float2*)&g_po[((size_t)(row0 + 8) * ASPL9 + s) * HD + col] =
                make_float2(oacc[n][2], oacc[n][3]);
        }
        lacc0 += __shfl_xor_sync(0xffffffffu, lacc0, 1);
        lacc0 += __shfl_xor_sync(0xffffffffu, lacc0, 2);
        lacc1 += __shfl_xor_sync(0xffffffffu, lacc1, 1);
        lacc1 += __shfl_xor_sync(0xffffffffu, lacc1, 2);
        if (tig == 0) {
            g_pml[row0 * ASPL9 + s]       = lacc0;
            g_pml[(row0 + 8) * ASPL9 + s] = lacc1;
        }
    }
}

/* ------------------------------------------------------------------ */
__global__ void combine9()
{
    int b = blockIdx.x, tid = threadIdx.x;   /* 128 threads */
    int r = tid >> 1, half = tid & 1;
    float lt = 0.f;
#pragma unroll
    for (int s = 0; s < ASPL9; s++) lt += g_pml[(b * 64 + r) * ASPL9 + s];
    float inv = 1.f / lt;
    int q = r & 3, h = r >> 2;
    float* dst = g_o + (size_t)(b * QL + q) * DIM + h * HD + half * 64;
    size_t pb = ((size_t)(b * 64 + r) * ASPL9) * HD + half * 64;
    for (int e = 0; e < 64; e += 4) {
        float4 acc = make_float4(0.f, 0.f, 0.f, 0.f);
#pragma unroll
        for (int s = 0; s < ASPL9; s++) {
            float4 v = *(const float4*)&g_po[pb + (size_t)s * HD + e];
            acc.x += v.x; acc.y += v.y; acc.z += v.z; acc.w += v.w;
        }
        acc.x *= inv; acc.y *= inv; acc.z *= inv; acc.w *= inv;
        *(float4*)&dst[e] = acc;
    }
}

/* ------------------------------------------------------------------ */
extern "C" void kernel_launch(void* const* d_in, const int* in_sizes, int n_in,
                              void* d_out, int out_size)
{
    const float* x         = (const float*)d_in[0];
    const float* attn_bias = (const float*)d_in[1];
    const float* cache_k   = (const float*)d_in[2];
    const float* cache_v   = (const float*)d_in[3];
    const float* wq        = (const float*)d_in[4];
    const float* bq        = (const float*)d_in[5];
    const float* wk        = (const float*)d_in[6];
    const float* bk        = (const float*)d_in[7];
    const float* wv        = (const float*)d_in[8];
    const float* bv        = (const float*)d_in[9];
    const float* wo        = (const float*)d_in[10];
    const float* bo        = (const float*)d_in[11];
    float*       out       = (float*)d_out;

    cudaFuncSetAttribute(attn7,
                         cudaFuncAttributeMaxDynamicSharedMemorySize, SMEM7);

    float* go_ptr = nullptr;
    cudaGetSymbolAddress((void**)&go_ptr, g_o);

    /* 1) QKV projections: K-split tensor GEMMs -> partials -> reduce */
    pgemm3<<<dim3(64, 2, KSPL), 128>>>(x, wq, 2048, 0);
    pgemm3<<<dim3(4, 2, KSPL),  128>>>(x, wk, 128,  2048);
    pgemm3<<<dim3(4, 2, KSPL),  128>>>(x, wv, 128,  2176);
    reduce_qkv4<<<288, 256>>>(bq, bk, bv);

    /* 2) tensor-core flash attention, 9 balanced KV splits */
    attn7<<<dim3(ASPL9, B_), 128, SMEM7>>>(attn_bias, cache_k, cache_v);

    /* 3) combine splits */
    combine9<<<B_, 128>>>();

    /* 4) output projection: K-split tensor GEMM -> partials -> reduce */
    pgemm3<<<dim3(64, 2, KSPL), 128>>>(go_ptr, wo, DIM, 0);
    reduce_out4<<<256, 256>>>(bo, out);
}